// round 8
// baseline (speedup 1.0000x reference)
#include <cuda_runtime.h>

#define STRIDE   10
#define NF       128
#define PAIRS    8128      // 128*127/2
#define NTASKS   12        // 16-row blocks x 64-col chunks covering lower triangle
#define THREADS  384       // 12 warps, exactly 1 task each

// task -> (16-row block index, 64-col chunk index)
__constant__ unsigned char c_bi[NTASKS] = {0,1,2,3,4,4,5,5,6,6,7,7};
__constant__ unsigned char c_jc[NTASKS] = {0,0,0,0,0,1,0,1,0,1,0,1};

__global__ __launch_bounds__(THREADS, 3)   // 56-reg cap: 3 CTAs/SM, no spills (R5-verified)
void corr_win_kernel(const float* __restrict__ x, float* __restrict__ out)
{
    __shared__ float ms[STRIDE][NF];   // normalized columns: (x-mean)/||x-mean||

    const int w    = blockIdx.x;       // window = b*100 + l
    const int tid  = threadIdx.x;
    const int warp = tid >> 5;
    const int lane = tid & 31;
    const float* __restrict__ xw = x + (size_t)w * (STRIDE * NF);

    // ---- Phase 1: load column, center, scale by 1/||.||, store to smem ---
    if (tid < NF) {
        float v[STRIDE];
        #pragma unroll
        for (int s = 0; s < STRIDE; ++s) v[s] = __ldcs(&xw[s * NF + tid]);
        float sum = 0.f;
        #pragma unroll
        for (int s = 0; s < STRIDE; ++s) sum += v[s];
        const float mean = sum * (1.0f / STRIDE);
        float s2 = 0.f;
        #pragma unroll
        for (int s = 0; s < STRIDE; ++s) {
            v[s] -= mean;
            s2 = fmaf(v[s], v[s], s2);
        }
        const float invn = (s2 > 0.f) ? rsqrtf(s2) : 0.f;  // divide_no_nan
        #pragma unroll
        for (int s = 0; s < STRIDE; ++s) ms[s][tid] = v[s] * invn;
    }
    __syncthreads();

    float* __restrict__ ow = out + (size_t)w * PAIRS;

    // ---- Phase 2: one 16x64 warp tile, packed f32x2 FMAs ------------------
    const int i0 = (int)c_bi[warp] * 16;
    const int jb = (int)c_jc[warp] * 64;
    const int j0 = jb + lane;          // coalesced column 1
    const int j1 = jb + 32 + lane;     // coalesced column 2

    // 8 packed accs per column set = 16 rows paired (i, i+1)
    unsigned long long acc0[8], acc1[8];
    #pragma unroll
    for (int p = 0; p < 8; ++p) { acc0[p] = 0ULL; acc1[p] = 0ULL; }

    #pragma unroll
    for (int s = 0; s < STRIDE; ++s) {
        const float b0 = ms[s][j0];    // coalesced, 1 wavefront
        const float b1 = ms[s][j1];    // coalesced, 1 wavefront
        unsigned long long bb0, bb1;   // (b,b) packed
        asm("mov.b64 %0, {%1, %1};" : "=l"(bb0) : "r"(__float_as_uint(b0)));
        asm("mov.b64 %0, {%1, %1};" : "=l"(bb1) : "r"(__float_as_uint(b1)));
        #pragma unroll
        for (int q = 0; q < 4; ++q) {
            // broadcast LDS.128 = two row-pair f32x2 operands, no repack
            const ulonglong2 A = *(const ulonglong2*)&ms[s][i0 + 4 * q];
            asm("fma.rn.f32x2 %0, %1, %2, %0;" : "+l"(acc0[2*q  ]) : "l"(A.x), "l"(bb0));
            asm("fma.rn.f32x2 %0, %1, %2, %0;" : "+l"(acc1[2*q  ]) : "l"(A.x), "l"(bb1));
            asm("fma.rn.f32x2 %0, %1, %2, %0;" : "+l"(acc0[2*q+1]) : "l"(A.y), "l"(bb0));
            asm("fma.rn.f32x2 %0, %1, %2, %0;" : "+l"(acc1[2*q+1]) : "l"(A.y), "l"(bb1));
        }
    }

    // ---- Phase 3: stores, incremental triangular base, full/partial ------
    int i    = i0;
    int base = (i0 * (i0 - 1)) >> 1;
    if (jb + 64 <= i0) {
        // fully interior tile: all 2x16 stores unconditional
        #pragma unroll
        for (int p = 0; p < 8; ++p) {
            unsigned int l0, h0, l1, h1;
            asm("mov.b64 {%0, %1}, %2;" : "=r"(l0), "=r"(h0) : "l"(acc0[p]));
            asm("mov.b64 {%0, %1}, %2;" : "=r"(l1), "=r"(h1) : "l"(acc1[p]));
            __stcs(&ow[base + j0], __uint_as_float(l0));
            __stcs(&ow[base + j1], __uint_as_float(l1));
            base += i; ++i;
            __stcs(&ow[base + j0], __uint_as_float(h0));
            __stcs(&ow[base + j1], __uint_as_float(h1));
            base += i; ++i;
        }
    } else {
        #pragma unroll
        for (int p = 0; p < 8; ++p) {
            unsigned int l0, h0, l1, h1;
            asm("mov.b64 {%0, %1}, %2;" : "=r"(l0), "=r"(h0) : "l"(acc0[p]));
            asm("mov.b64 {%0, %1}, %2;" : "=r"(l1), "=r"(h1) : "l"(acc1[p]));
            if (j0 < i) __stcs(&ow[base + j0], __uint_as_float(l0));
            if (j1 < i) __stcs(&ow[base + j1], __uint_as_float(l1));
            base += i; ++i;
            if (j0 < i) __stcs(&ow[base + j0], __uint_as_float(h0));
            if (j1 < i) __stcs(&ow[base + j1], __uint_as_float(h1));
            base += i; ++i;
        }
    }
}

extern "C" void kernel_launch(void* const* d_in, const int* in_sizes, int n_in,
                              void* d_out, int out_size)
{
    const float* x = (const float*)d_in[0];
    float* out     = (float*)d_out;
    int n_windows  = in_sizes[0] / (STRIDE * NF);   // 6400
    corr_win_kernel<<<n_windows, THREADS>>>(x, out);
}